// round 1
// baseline (speedup 1.0000x reference)
#include <cuda_runtime.h>
#include <cuda_bf16.h>
#include <math.h>

// Problem constants
#define BB 2
#define SS 2048
#define DD 2048
#define HH 16
#define HD 128
#define TOPK 256
#define HIDDEN 8192
#define RSEL (BB*TOPK)      // 512 selected rows total
#define RTOT (RSEL + BB)    // + 1 shared row per batch = 514
#define EPS 1e-6f

// ---------------- scratch (static device globals; no allocs allowed) ----------------
__device__ float g_tw[BB*SS];
__device__ int   g_idx[BB*TOPK];
__device__ int   g_rank[BB*SS];
__device__ float g_xn[RSEL*DD];
__device__ float g_q[RSEL*DD];
__device__ float g_k[RSEL*DD];
__device__ float g_v[RSEL*DD];
__device__ float g_attn[RTOT*DD];
__device__ float g_h[RTOT*DD];
__device__ float g_hn[RTOT*DD];
__device__ float g_u1[RTOT*HIDDEN];
__device__ float g_u3[RTOT*HIDDEN];
__device__ float g_outrows[RTOT*DD];

// ---------------- 1. router: tw = x @ router_w ----------------
__global__ void router_kernel(const float* __restrict__ x, const float* __restrict__ rw,
                              float* __restrict__ tw, float* __restrict__ dout,
                              size_t off_tw, size_t out_size) {
    int tok = blockIdx.x;            // 0..B*S-1
    __shared__ float red[256];
    float s = 0.f;
    const float* xr = x + (size_t)tok * DD;
    for (int c = threadIdx.x; c < DD; c += 256) s += xr[c] * rw[c];
    red[threadIdx.x] = s; __syncthreads();
    for (int o = 128; o > 0; o >>= 1) {
        if (threadIdx.x < o) red[threadIdx.x] += red[threadIdx.x + o];
        __syncthreads();
    }
    if (threadIdx.x == 0) {
        tw[tok] = red[0];
        if (off_tw + (size_t)tok < out_size) dout[off_tw + tok] = red[0];
    }
}

// ---------------- 2. top-k via full bitonic sort (desc value, asc index ties) ----------------
__global__ void topk_kernel(const float* __restrict__ tw, int* __restrict__ gidx,
                            float* __restrict__ dout, size_t off_idx, size_t out_size) {
    __shared__ float v[SS];
    __shared__ int   id[SS];
    int b = blockIdx.x;
    int t = threadIdx.x;             // 1024 threads
    for (int i = t; i < SS; i += 1024) { v[i] = tw[b*SS + i]; id[i] = i; }
    __syncthreads();
    for (int k = 2; k <= SS; k <<= 1) {
        for (int j = k >> 1; j > 0; j >>= 1) {
            for (int i = t; i < SS; i += 1024) {
                int ixj = i ^ j;
                if (ixj > i) {
                    bool up = ((i & k) == 0);
                    float va = v[i], vb = v[ixj];
                    int   ia = id[i], ib = id[ixj];
                    bool aBeforeB = (va > vb) || (va == vb && ia < ib);
                    bool sw = up ? !aBeforeB : aBeforeB;
                    if (sw) { v[i]=vb; v[ixj]=va; id[i]=ib; id[ixj]=ia; }
                }
            }
            __syncthreads();
        }
    }
    for (int i = t; i < TOPK; i += 1024) {
        gidx[b*TOPK + i] = id[i];
        size_t o = off_idx + (size_t)b*TOPK + i;
        if (o < out_size) dout[o] = (float)id[i];
    }
}

// ---------------- 3. rank map ----------------
__global__ void rank_init(int* __restrict__ rank) {
    int i = blockIdx.x*256 + threadIdx.x;
    if (i < BB*SS) rank[i] = -1;
}
__global__ void rank_set(const int* __restrict__ gidx, int* __restrict__ rank) {
    int r = blockIdx.x*256 + threadIdx.x;
    if (r < RSEL) {
        int b = r / TOPK;
        rank[b*SS + gidx[r]] = r % TOPK;
    }
}

// ---------------- 4. gather + rmsnorm (attn_norm) ----------------
__global__ void rmsnorm_gather(const float* __restrict__ x, const int* __restrict__ gidx,
                               const float* __restrict__ w, float* __restrict__ out) {
    int r = blockIdx.x;              // 0..511
    int b = r / TOPK;
    int pos = gidx[r];
    const float* xr = x + ((size_t)b*SS + pos) * DD;
    __shared__ float red[256];
    float s = 0.f;
    for (int c = threadIdx.x; c < DD; c += 256) { float v = xr[c]; s += v*v; }
    red[threadIdx.x] = s; __syncthreads();
    for (int o = 128; o > 0; o >>= 1) {
        if (threadIdx.x < o) red[threadIdx.x] += red[threadIdx.x + o];
        __syncthreads();
    }
    float rms = rsqrtf(red[0] / (float)DD + EPS);
    float* orow = out + (size_t)r * DD;
    for (int c = threadIdx.x; c < DD; c += 256) orow[c] = xr[c] * rms * w[c];
}

// ---------------- generic rmsnorm over rows ----------------
__global__ void rmsnorm_rows(const float* __restrict__ in, const float* __restrict__ w,
                             float* __restrict__ out) {
    int r = blockIdx.x;
    const float* xr = in + (size_t)r * DD;
    __shared__ float red[256];
    float s = 0.f;
    for (int c = threadIdx.x; c < DD; c += 256) { float v = xr[c]; s += v*v; }
    red[threadIdx.x] = s; __syncthreads();
    for (int o = 128; o > 0; o >>= 1) {
        if (threadIdx.x < o) red[threadIdx.x] += red[threadIdx.x + o];
        __syncthreads();
    }
    float rms = rsqrtf(red[0] / (float)DD + EPS);
    float* orow = out + (size_t)r * DD;
    for (int c = threadIdx.x; c < DD; c += 256) orow[c] = xr[c] * rms * w[c];
}

// ---------------- 5. tiled fp32 GEMM: C[M,N] = A[M,K] @ B[K,N], row-major ----------------
#define GBM 64
#define GBN 64
#define GBK 16
__global__ void gemm_kernel(const float* __restrict__ A, const float* __restrict__ Bm,
                            float* __restrict__ C, int M, int K, int N) {
    __shared__ float As[GBK][GBM+1];
    __shared__ float Bs[GBK][GBN];
    int tid = threadIdx.x;           // 256
    int tx = tid & 15, ty = tid >> 4;
    int bm = blockIdx.y * GBM, bn = blockIdx.x * GBN;
    float acc[4][4] = {};
    for (int k0 = 0; k0 < K; k0 += GBK) {
        #pragma unroll
        for (int i = 0; i < 4; i++) {
            int l = tid + 256*i;                 // 0..1023
            int m = l >> 4, kk = l & 15;
            int gm = bm + m;
            As[kk][m] = (gm < M) ? A[(size_t)gm*K + k0 + kk] : 0.f;
        }
        #pragma unroll
        for (int i = 0; i < 4; i++) {
            int l = tid + 256*i;
            int kk = l >> 6, n = l & 63;
            Bs[kk][n] = Bm[(size_t)(k0+kk)*N + bn + n];
        }
        __syncthreads();
        #pragma unroll
        for (int kk = 0; kk < GBK; kk++) {
            float a[4], bv[4];
            #pragma unroll
            for (int i = 0; i < 4; i++) a[i]  = As[kk][ty*4+i];
            #pragma unroll
            for (int j = 0; j < 4; j++) bv[j] = Bs[kk][tx*4+j];
            #pragma unroll
            for (int i = 0; i < 4; i++)
                #pragma unroll
                for (int j = 0; j < 4; j++) acc[i][j] += a[i]*bv[j];
        }
        __syncthreads();
    }
    #pragma unroll
    for (int i = 0; i < 4; i++) {
        int gm = bm + ty*4 + i;
        if (gm >= M) continue;
        #pragma unroll
        for (int j = 0; j < 4; j++) C[(size_t)gm*N + bn + tx*4 + j] = acc[i][j];
    }
}

// ---------------- 6. rotary on q and k ----------------
__global__ void rotary_kernel(float* __restrict__ q, float* __restrict__ k,
                              const int* __restrict__ gidx, const float* __restrict__ freqs,
                              const int* __restrict__ startp) {
    int r = blockIdx.x;              // 0..511
    int pos = startp[0] + gidx[r];
    const float* f = freqs + (size_t)pos * HD;   // 64 (cos,sin) pairs
    size_t base = (size_t)r * DD;
    for (int e = threadIdx.x; e < HH*HD/2; e += 256) {
        int hp = e & 63;                          // pair within head
        float c = f[hp*2], sn = f[hp*2+1];
        size_t i0 = base + (size_t)e*2;
        float q0 = q[i0], q1 = q[i0+1];
        q[i0]   = q0*c - q1*sn;
        q[i0+1] = q0*sn + q1*c;
        float k0 = k[i0], k1 = k[i0+1];
        k[i0]   = k0*c - k1*sn;
        k[i0+1] = k0*sn + k1*c;
    }
}

// ---------------- 7. attention among selected tokens ----------------
#define QT 64
#define KC 64
#define QS_STRIDE 129
#define SC_STRIDE 257
__global__ void attn_kernel(const float* __restrict__ q, const float* __restrict__ k,
                            const float* __restrict__ v, float* __restrict__ attn) {
    extern __shared__ float sm[];
    float* qs = sm;                          // QT*129
    float* kt = qs + QT*QS_STRIDE;           // KC*129
    float* sc = kt + KC*QS_STRIDE;           // QT*257
    int qt = blockIdx.x, h = blockIdx.y, b = blockIdx.z;
    int t = threadIdx.x;                     // 256
    int rb = b * TOPK;
    // load Q tile
    for (int l = t; l < QT*HD; l += 256) {
        int qi = l / HD, d = l % HD;
        qs[qi*QS_STRIDE + d] = q[((size_t)(rb + qt*QT + qi))*DD + h*HD + d];
    }
    const float scale = 0.08838834764831845f;  // 1/sqrt(128)
    int qi = t >> 2;
    // score phase
    {
        int kj0 = (t & 3) * 16;
        for (int kc = 0; kc < TOPK/KC; kc++) {
            __syncthreads();
            for (int l = t; l < KC*HD; l += 256) {
                int kj = l / HD, d = l % HD;
                kt[kj*QS_STRIDE + d] = k[((size_t)(rb + kc*KC + kj))*DD + h*HD + d];
            }
            __syncthreads();
            float acc[16];
            #pragma unroll
            for (int n = 0; n < 16; n++) acc[n] = 0.f;
            for (int d = 0; d < HD; d++) {
                float qv = qs[qi*QS_STRIDE + d];
                #pragma unroll
                for (int n = 0; n < 16; n++)
                    acc[n] += qv * kt[(kj0+n)*QS_STRIDE + d];
            }
            #pragma unroll
            for (int n = 0; n < 16; n++)
                sc[qi*SC_STRIDE + kc*KC + kj0 + n] = acc[n] * scale;
        }
    }
    __syncthreads();
    // softmax (one thread per query row)
    if (t < QT) {
        float m = -1e30f;
        for (int j = 0; j < TOPK; j++) m = fmaxf(m, sc[t*SC_STRIDE + j]);
        float s = 0.f;
        for (int j = 0; j < TOPK; j++) {
            float e = expf(sc[t*SC_STRIDE + j] - m);
            sc[t*SC_STRIDE + j] = e; s += e;
        }
        float inv = 1.f / s;
        for (int j = 0; j < TOPK; j++) sc[t*SC_STRIDE + j] *= inv;
    }
    __syncthreads();
    // AV phase
    int d0 = (t & 3) * 32;
    float oacc[32];
    #pragma unroll
    for (int i = 0; i < 32; i++) oacc[i] = 0.f;
    for (int kc = 0; kc < TOPK/KC; kc++) {
        __syncthreads();
        for (int l = t; l < KC*HD; l += 256) {
            int kj = l / HD, d = l % HD;
            kt[kj*QS_STRIDE + d] = v[((size_t)(rb + kc*KC + kj))*DD + h*HD + d];
        }
        __syncthreads();
        for (int j = 0; j < KC; j++) {
            float p = sc[qi*SC_STRIDE + kc*KC + j];
            #pragma unroll
            for (int dd = 0; dd < 32; dd++)
                oacc[dd] += p * kt[j*QS_STRIDE + d0 + dd];
        }
    }
    float* orow = attn + ((size_t)(rb + qt*QT + qi))*DD + h*HD + d0;
    #pragma unroll
    for (int dd = 0; dd < 32; dd++) orow[dd] = oacc[dd];
}

// ---------------- 8. mean of selected V per (b,h) -> shared attn row ----------------
__global__ void meanv_kernel(const float* __restrict__ v, float* __restrict__ attn) {
    int h = blockIdx.x, b = blockIdx.y;
    int d = threadIdx.x;                     // 128
    float s = 0.f;
    for (int j = 0; j < TOPK; j++)
        s += v[((size_t)(b*TOPK + j))*DD + h*HD + d];
    attn[((size_t)(RSEL + b))*DD + h*HD + d] = s * (1.f / TOPK);
}

// ---------------- 9. h = masked_input(x) + attn@wo (add x for selected rows) ----------------
__global__ void addx_kernel(const float* __restrict__ x, const int* __restrict__ gidx,
                            float* __restrict__ h) {
    int r = blockIdx.x;                      // 0..511
    int b = r / TOPK;
    int pos = gidx[r];
    const float* xr = x + ((size_t)b*SS + pos) * DD;
    float* hr = h + (size_t)r * DD;
    for (int c = threadIdx.x; c < DD; c += 256) hr[c] += xr[c];
}

// ---------------- 10. silu(u1)*u3 in place ----------------
__global__ void silu_mul(float* __restrict__ u1, const float* __restrict__ u3, size_t n) {
    size_t i = (size_t)blockIdx.x*256 + threadIdx.x;
    if (i < n) {
        float a = u1[i];
        float s = a / (1.f + expf(-a));
        u1[i] = s * u3[i];
    }
}

// ---------------- 11. scatter rows to full (B,S,D) output ----------------
__global__ void scatter_out(const float* __restrict__ rows, const int* __restrict__ rank,
                            float* __restrict__ dout) {
    int tok = blockIdx.x;                    // 0..B*S-1
    int b = tok / SS;
    int rk = rank[tok];
    int srow = (rk >= 0) ? (b*TOPK + rk) : (RSEL + b);
    const float4* s4 = (const float4*)(rows + (size_t)srow * DD);
    float4* d4 = (float4*)(dout + (size_t)tok * DD);
    for (int c = threadIdx.x; c < DD/4; c += 256) d4[c] = s4[c];
}

// ---------------- launch ----------------
extern "C" void kernel_launch(void* const* d_in, const int* in_sizes, int n_in,
                              void* d_out, int out_size) {
    const float* x        = (const float*)d_in[0];
    const int*   start_p  = (const int*)  d_in[1];
    const float* freqs    = (const float*)d_in[2];
    const float* router_w = (const float*)d_in[3];
    const float* wq       = (const float*)d_in[4];
    const float* wk       = (const float*)d_in[5];
    const float* wv       = (const float*)d_in[6];
    const float* wo       = (const float*)d_in[7];
    const float* w1       = (const float*)d_in[8];
    const float* w2       = (const float*)d_in[9];
    const float* w3       = (const float*)d_in[10];
    const float* attn_nw  = (const float*)d_in[11];
    const float* ffn_nw   = (const float*)d_in[12];
    float* out = (float*)d_out;

    size_t off_tw  = (size_t)BB*SS*DD;        // 8,388,608
    size_t off_idx = off_tw + (size_t)BB*SS;  // +4096
    size_t osz = (size_t)out_size;

    // resolve device-global scratch addresses
    float *tw, *xn, *q, *k, *v, *attn, *h, *hn, *u1, *u3, *outrows;
    int *idx, *rank;
    cudaGetSymbolAddress((void**)&tw,   g_tw);
    cudaGetSymbolAddress((void**)&idx,  g_idx);
    cudaGetSymbolAddress((void**)&rank, g_rank);
    cudaGetSymbolAddress((void**)&xn,   g_xn);
    cudaGetSymbolAddress((void**)&q,    g_q);
    cudaGetSymbolAddress((void**)&k,    g_k);
    cudaGetSymbolAddress((void**)&v,    g_v);
    cudaGetSymbolAddress((void**)&attn, g_attn);
    cudaGetSymbolAddress((void**)&h,    g_h);
    cudaGetSymbolAddress((void**)&hn,   g_hn);
    cudaGetSymbolAddress((void**)&u1,   g_u1);
    cudaGetSymbolAddress((void**)&u3,   g_u3);
    cudaGetSymbolAddress((void**)&outrows, g_outrows);

    // attention kernel needs >48KB dynamic smem
    int attn_smem = (QT*QS_STRIDE + KC*QS_STRIDE + QT*SC_STRIDE) * 4;
    cudaFuncSetAttribute(attn_kernel, cudaFuncAttributeMaxDynamicSharedMemorySize, attn_smem);

    // 1. router
    router_kernel<<<BB*SS, 256>>>(x, router_w, tw, out, off_tw, osz);
    // 2. top-k
    topk_kernel<<<BB, 1024>>>(tw, idx, out, off_idx, osz);
    // 3. rank map
    rank_init<<<(BB*SS + 255)/256, 256>>>(rank);
    rank_set<<<(RSEL + 255)/256, 256>>>(idx, rank);
    // 4. gather + rmsnorm(attn)
    rmsnorm_gather<<<RSEL, 256>>>(x, idx, attn_nw, xn);
    // 5. QKV projections (M=512)
    gemm_kernel<<<dim3(DD/GBN, RSEL/GBM), 256>>>(xn, wq, q, RSEL, DD, DD);
    gemm_kernel<<<dim3(DD/GBN, RSEL/GBM), 256>>>(xn, wk, k, RSEL, DD, DD);
    gemm_kernel<<<dim3(DD/GBN, RSEL/GBM), 256>>>(xn, wv, v, RSEL, DD, DD);
    // 6. rotary
    rotary_kernel<<<RSEL, 256>>>(q, k, idx, freqs, start_p);
    // 7. attention over selected tokens
    attn_kernel<<<dim3(TOPK/QT, HH, BB), 256, attn_smem>>>(q, k, v, attn);
    // 8. shared row = mean of selected V
    meanv_kernel<<<dim3(HH, BB), HD>>>(v, attn);
    // 9. wo projection on 514 rows, then add masked_input for selected rows
    gemm_kernel<<<dim3(DD/GBN, (RTOT+GBM-1)/GBM), 256>>>(attn, wo, h, RTOT, DD, DD);
    addx_kernel<<<RSEL, 256>>>(x, idx, h);
    // 10. ffn rmsnorm
    rmsnorm_rows<<<RTOT, 256>>>(h, ffn_nw, hn);
    // 11. FFN
    gemm_kernel<<<dim3(HIDDEN/GBN, (RTOT+GBM-1)/GBM), 256>>>(hn, w1, u1, RTOT, DD, HIDDEN);
    gemm_kernel<<<dim3(HIDDEN/GBN, (RTOT+GBM-1)/GBM), 256>>>(hn, w3, u3, RTOT, DD, HIDDEN);
    {
        size_t n = (size_t)RTOT * HIDDEN;
        silu_mul<<<(unsigned)((n + 255)/256), 256>>>(u1, u3, n);
    }
    gemm_kernel<<<dim3(DD/GBN, (RTOT+GBM-1)/GBM), 256>>>(u1, w2, outrows, RTOT, HIDDEN, DD);
    // 12. scatter to (B,S,D)
    scatter_out<<<BB*SS, 256>>>(outrows, rank, out);
}

// round 4
// speedup vs baseline: 1.3723x; 1.3723x over previous
#include <cuda_runtime.h>
#include <cuda_bf16.h>
#include <math.h>
#include <cstdint>

// Problem constants
#define BB 2
#define SS 2048
#define DD 2048
#define HH 16
#define HD 128
#define TOPK 256
#define HIDDEN 8192
#define RSEL (BB*TOPK)      // 512 selected rows total
#define RTOT (RSEL + BB)    // + 1 shared row per batch = 514
#define EPS 1e-6f

// ---------------- scratch (static device globals; no allocs allowed) ----------------
__device__ float g_tw[BB*SS];
__device__ int   g_idx[BB*TOPK];
__device__ int   g_rank[BB*SS];
__device__ float g_xn[RSEL*DD];
__device__ float g_q[RSEL*DD];
__device__ float g_k[RSEL*DD];
__device__ float g_v[RSEL*DD];
__device__ float g_attn[RTOT*DD];
__device__ float g_h[RTOT*DD];
__device__ float g_hn[RTOT*DD];
__device__ float g_u1[RTOT*HIDDEN];
__device__ float g_u3[RTOT*HIDDEN];
__device__ float g_outrows[RTOT*DD];

// ================= helpers =================
__device__ __forceinline__ uint32_t smem_u32(const void* p) {
    uint32_t a;
    asm("{ .reg .u64 t; cvta.to.shared.u64 t, %1; cvt.u32.u64 %0, t; }" : "=r"(a) : "l"(p));
    return a;
}
__device__ __forceinline__ void cpa16(uint32_t dst, const float* src, int sz) {
    asm volatile("cp.async.cg.shared.global [%0], [%1], 16, %2;" :: "r"(dst), "l"(src), "r"(sz) : "memory");
}
#define CP_COMMIT() asm volatile("cp.async.commit_group;" ::: "memory")

__device__ __forceinline__ void mma_tf32(float* cc, const uint32_t* a, const uint32_t* b) {
    asm volatile(
        "mma.sync.aligned.m16n8k8.row.col.f32.tf32.tf32.f32 "
        "{%0,%1,%2,%3},{%4,%5,%6,%7},{%8,%9},{%0,%1,%2,%3};"
        : "+f"(cc[0]), "+f"(cc[1]), "+f"(cc[2]), "+f"(cc[3])
        : "r"(a[0]), "r"(a[1]), "r"(a[2]), "r"(a[3]), "r"(b[0]), "r"(b[1]));
}
// split fp32 -> (hi tf32, lo residual-as-tf32-bits)
__device__ __forceinline__ void tf32_split(float a, uint32_t& hi, uint32_t& lo) {
    uint32_t h;
    asm("cvt.rna.tf32.f32 %0, %1;" : "=r"(h) : "f"(a));
    hi = h;
    lo = __float_as_uint(a - __uint_as_float(h));
}

// ================= 3xTF32 mma.sync GEMM: C[M,N] = A[M,K] @ B[K,N] (row-major) =================
#define BM 128
#define BN 128
#define BKK 32
#define SA_STRIDE 36            // floats; bank-conflict-free A fragment loads
#define SB_STRIDE 136           // floats; bank-conflict-free B fragment loads
#define A_FLOATS (BM*SA_STRIDE) // 4608
#define B_FLOATS (BKK*SB_STRIDE)// 4352
#define STAGE_FLOATS (A_FLOATS + B_FLOATS)  // 8960
#define GEMM_SMEM (2*STAGE_FLOATS*4)        // 71680 bytes

__device__ __forceinline__ void load_stage(
    const float* __restrict__ A, const float* __restrict__ Bm,
    uint32_t sbase, int buf, int bm, int bn, int k0, int M, int K, int N, int tid)
{
    uint32_t aoff = sbase + (uint32_t)(buf * STAGE_FLOATS) * 4u;
    uint32_t boff = aoff + (uint32_t)A_FLOATS * 4u;
    // A: 128 rows x 32 cols, 4 float4 per thread
    #pragma unroll
    for (int i = 0; i < 4; i++) {
        int idx = tid + 256 * i;            // 0..1023
        int row = idx >> 3;
        int kc  = (idx & 7) * 4;
        int gm  = bm + row;
        const float* src = A + (size_t)gm * K + k0 + kc;
        cpa16(aoff + (uint32_t)(row * SA_STRIDE + kc) * 4u, src, (gm < M) ? 16 : 0);
    }
    // B: 32 rows(k) x 128 cols(n), 4 float4 per thread
    #pragma unroll
    for (int i = 0; i < 4; i++) {
        int idx = tid + 256 * i;
        int k  = idx >> 5;
        int nc = (idx & 31) * 4;
        const float* src = Bm + (size_t)(k0 + k) * N + bn + nc;
        cpa16(boff + (uint32_t)(k * SB_STRIDE + nc) * 4u, src, 16);
    }
    CP_COMMIT();
}

__global__ void __launch_bounds__(256) mma_gemm(
    const float* __restrict__ A,
    const float* __restrict__ B0c, const float* __restrict__ B1c, const float* __restrict__ B2c,
    float* __restrict__ C0c, float* __restrict__ C1c, float* __restrict__ C2c,
    int M, int K, int N)
{
    extern __shared__ float sm[];
    const float* Bm = (blockIdx.z == 0) ? B0c : ((blockIdx.z == 1) ? B1c : B2c);
    float*       C  = (blockIdx.z == 0) ? C0c : ((blockIdx.z == 1) ? C1c : C2c);
    uint32_t sbase = smem_u32(sm);
    int tid = threadIdx.x;
    int bm = blockIdx.y * BM, bn = blockIdx.x * BN;
    int lane = tid & 31, wid = tid >> 5;
    int r = lane >> 2, c = lane & 3;
    int m_base = (wid >> 2) * 64;    // warp row: 0 or 64
    int n_base = (wid & 3) * 32;     // warp col: 0,32,64,96

    float acc[4][4][4];
    #pragma unroll
    for (int mt = 0; mt < 4; mt++)
        #pragma unroll
        for (int nt = 0; nt < 4; nt++)
            #pragma unroll
            for (int q = 0; q < 4; q++) acc[mt][nt][q] = 0.f;

    int T = K / BKK;
    load_stage(A, Bm, sbase, 0, bm, bn, 0, M, K, N, tid);

    for (int i = 0; i < T; i++) {
        int buf = i & 1;
        if (i + 1 < T) {
            load_stage(A, Bm, sbase, buf ^ 1, bm, bn, (i + 1) * BKK, M, K, N, tid);
            asm volatile("cp.async.wait_group 1;" ::: "memory");
        } else {
            asm volatile("cp.async.wait_group 0;" ::: "memory");
        }
        __syncthreads();

        const float* Asm = sm + buf * STAGE_FLOATS;
        const float* Bsm = Asm + A_FLOATS;
        #pragma unroll
        for (int ks = 0; ks < 4; ks++) {
            int kc = ks * 8;
            uint32_t afh[4][4], afl[4][4];
            #pragma unroll
            for (int mt = 0; mt < 4; mt++) {
                int row0 = m_base + mt * 16 + r;
                float a0 = Asm[row0 * SA_STRIDE + kc + c];
                float a1 = Asm[(row0 + 8) * SA_STRIDE + kc + c];
                float a2 = Asm[row0 * SA_STRIDE + kc + c + 4];
                float a3 = Asm[(row0 + 8) * SA_STRIDE + kc + c + 4];
                tf32_split(a0, afh[mt][0], afl[mt][0]);
                tf32_split(a1, afh[mt][1], afl[mt][1]);
                tf32_split(a2, afh[mt][2], afl[mt][2]);
                tf32_split(a3, afh[mt][3], afl[mt][3]);
            }
            uint32_t bfh[4][2], bfl[4][2];
            #pragma unroll
            for (int nt = 0; nt < 4; nt++) {
                int n = n_base + nt * 8 + r;
                float b0 = Bsm[(kc + c) * SB_STRIDE + n];
                float b1 = Bsm[(kc + c + 4) * SB_STRIDE + n];
                tf32_split(b0, bfh[nt][0], bfl[nt][0]);
                tf32_split(b1, bfh[nt][1], bfl[nt][1]);
            }
            #pragma unroll
            for (int mt = 0; mt < 4; mt++)
                #pragma unroll
                for (int nt = 0; nt < 4; nt++) {
                    mma_tf32(acc[mt][nt], afl[mt], bfh[nt]);
                    mma_tf32(acc[mt][nt], afh[mt], bfl[nt]);
                    mma_tf32(acc[mt][nt], afh[mt], bfh[nt]);
                }
        }
        __syncthreads();
    }

    // epilogue: c0,c1 -> (row, col..col+1); c2,c3 -> (row+8)
    #pragma unroll
    for (int mt = 0; mt < 4; mt++) {
        int row0 = bm + m_base + mt * 16 + r;
        #pragma unroll
        for (int nt = 0; nt < 4; nt++) {
            int col = bn + n_base + nt * 8 + c * 2;
            if (row0 < M) {
                float2 v = make_float2(acc[mt][nt][0], acc[mt][nt][1]);
                *(float2*)(C + (size_t)row0 * N + col) = v;
            }
            if (row0 + 8 < M) {
                float2 v = make_float2(acc[mt][nt][2], acc[mt][nt][3]);
                *(float2*)(C + (size_t)(row0 + 8) * N + col) = v;
            }
        }
    }
}

// ---------------- 1. router: tw = x @ router_w ----------------
__global__ void router_kernel(const float* __restrict__ x, const float* __restrict__ rw,
                              float* __restrict__ tw, float* __restrict__ dout,
                              size_t off_tw, size_t out_size) {
    int tok = blockIdx.x;
    __shared__ float red[256];
    float s = 0.f;
    const float* xr = x + (size_t)tok * DD;
    for (int c = threadIdx.x; c < DD; c += 256) s += xr[c] * rw[c];
    red[threadIdx.x] = s; __syncthreads();
    for (int o = 128; o > 0; o >>= 1) {
        if (threadIdx.x < o) red[threadIdx.x] += red[threadIdx.x + o];
        __syncthreads();
    }
    if (threadIdx.x == 0) {
        tw[tok] = red[0];
        if (off_tw + (size_t)tok < out_size) dout[off_tw + tok] = red[0];
    }
}

// ---------------- 2. top-k via full bitonic sort (desc value, asc index ties) ----------------
__global__ void topk_kernel(const float* __restrict__ tw, int* __restrict__ gidx,
                            float* __restrict__ dout, size_t off_idx, size_t out_size) {
    __shared__ float v[SS];
    __shared__ int   id[SS];
    int b = blockIdx.x;
    int t = threadIdx.x;
    for (int i = t; i < SS; i += 1024) { v[i] = tw[b*SS + i]; id[i] = i; }
    __syncthreads();
    for (int k = 2; k <= SS; k <<= 1) {
        for (int j = k >> 1; j > 0; j >>= 1) {
            for (int i = t; i < SS; i += 1024) {
                int ixj = i ^ j;
                if (ixj > i) {
                    bool up = ((i & k) == 0);
                    float va = v[i], vb = v[ixj];
                    int   ia = id[i], ib = id[ixj];
                    bool aBeforeB = (va > vb) || (va == vb && ia < ib);
                    bool sw = up ? !aBeforeB : aBeforeB;
                    if (sw) { v[i]=vb; v[ixj]=va; id[i]=ib; id[ixj]=ia; }
                }
            }
            __syncthreads();
        }
    }
    for (int i = t; i < TOPK; i += 1024) {
        gidx[b*TOPK + i] = id[i];
        size_t o = off_idx + (size_t)b*TOPK + i;
        if (o < out_size) dout[o] = (float)id[i];
    }
}

// ---------------- 3. rank map ----------------
__global__ void rank_init(int* __restrict__ rank) {
    int i = blockIdx.x*256 + threadIdx.x;
    if (i < BB*SS) rank[i] = -1;
}
__global__ void rank_set(const int* __restrict__ gidx, int* __restrict__ rank) {
    int r = blockIdx.x*256 + threadIdx.x;
    if (r < RSEL) {
        int b = r / TOPK;
        rank[b*SS + gidx[r]] = r % TOPK;
    }
}

// ---------------- 4. gather + rmsnorm (attn_norm) ----------------
__global__ void rmsnorm_gather(const float* __restrict__ x, const int* __restrict__ gidx,
                               const float* __restrict__ w, float* __restrict__ out) {
    int r = blockIdx.x;
    int b = r / TOPK;
    int pos = gidx[r];
    const float* xr = x + ((size_t)b*SS + pos) * DD;
    __shared__ float red[256];
    float s = 0.f;
    for (int c = threadIdx.x; c < DD; c += 256) { float v = xr[c]; s += v*v; }
    red[threadIdx.x] = s; __syncthreads();
    for (int o = 128; o > 0; o >>= 1) {
        if (threadIdx.x < o) red[threadIdx.x] += red[threadIdx.x + o];
        __syncthreads();
    }
    float rms = rsqrtf(red[0] / (float)DD + EPS);
    float* orow = out + (size_t)r * DD;
    for (int c = threadIdx.x; c < DD; c += 256) orow[c] = xr[c] * rms * w[c];
}

// ---------------- generic rmsnorm over rows ----------------
__global__ void rmsnorm_rows(const float* __restrict__ in, const float* __restrict__ w,
                             float* __restrict__ out) {
    int r = blockIdx.x;
    const float* xr = in + (size_t)r * DD;
    __shared__ float red[256];
    float s = 0.f;
    for (int c = threadIdx.x; c < DD; c += 256) { float v = xr[c]; s += v*v; }
    red[threadIdx.x] = s; __syncthreads();
    for (int o = 128; o > 0; o >>= 1) {
        if (threadIdx.x < o) red[threadIdx.x] += red[threadIdx.x + o];
        __syncthreads();
    }
    float rms = rsqrtf(red[0] / (float)DD + EPS);
    float* orow = out + (size_t)r * DD;
    for (int c = threadIdx.x; c < DD; c += 256) orow[c] = xr[c] * rms * w[c];
}

// ---------------- 6. rotary on q and k ----------------
__global__ void rotary_kernel(float* __restrict__ q, float* __restrict__ k,
                              const int* __restrict__ gidx, const float* __restrict__ freqs,
                              const int* __restrict__ startp) {
    int r = blockIdx.x;
    int pos = startp[0] + gidx[r];
    const float* f = freqs + (size_t)pos * HD;
    size_t base = (size_t)r * DD;
    for (int e = threadIdx.x; e < HH*HD/2; e += 256) {
        int hp = e & 63;
        float c = f[hp*2], sn = f[hp*2+1];
        size_t i0 = base + (size_t)e*2;
        float q0 = q[i0], q1 = q[i0+1];
        q[i0]   = q0*c - q1*sn;
        q[i0+1] = q0*sn + q1*c;
        float k0 = k[i0], k1 = k[i0+1];
        k[i0]   = k0*c - k1*sn;
        k[i0+1] = k0*sn + k1*c;
    }
}

// ---------------- 7. attention among selected tokens ----------------
#define QT 64
#define KC 64
#define QS_STRIDE 129
#define SC_STRIDE 257
__global__ void attn_kernel(const float* __restrict__ q, const float* __restrict__ k,
                            const float* __restrict__ v, float* __restrict__ attn) {
    extern __shared__ float smf[];
    float* qs = smf;
    float* kt = qs + QT*QS_STRIDE;
    float* sc = kt + KC*QS_STRIDE;
    int qt = blockIdx.x, h = blockIdx.y, b = blockIdx.z;
    int t = threadIdx.x;
    int rb = b * TOPK;
    for (int l = t; l < QT*HD; l += 256) {
        int qi = l / HD, d = l % HD;
        qs[qi*QS_STRIDE + d] = q[((size_t)(rb + qt*QT + qi))*DD + h*HD + d];
    }
    const float scale = 0.08838834764831845f;
    int qi = t >> 2;
    {
        int kj0 = (t & 3) * 16;
        for (int kc = 0; kc < TOPK/KC; kc++) {
            __syncthreads();
            for (int l = t; l < KC*HD; l += 256) {
                int kj = l / HD, d = l % HD;
                kt[kj*QS_STRIDE + d] = k[((size_t)(rb + kc*KC + kj))*DD + h*HD + d];
            }
            __syncthreads();
            float acc[16];
            #pragma unroll
            for (int n = 0; n < 16; n++) acc[n] = 0.f;
            for (int d = 0; d < HD; d++) {
                float qv = qs[qi*QS_STRIDE + d];
                #pragma unroll
                for (int n = 0; n < 16; n++)
                    acc[n] += qv * kt[(kj0+n)*QS_STRIDE + d];
            }
            #pragma unroll
            for (int n = 0; n < 16; n++)
                sc[qi*SC_STRIDE + kc*KC + kj0 + n] = acc[n] * scale;
        }
    }
    __syncthreads();
    if (t < QT) {
        float m = -1e30f;
        for (int j = 0; j < TOPK; j++) m = fmaxf(m, sc[t*SC_STRIDE + j]);
        float s = 0.f;
        for (int j = 0; j < TOPK; j++) {
            float e = expf(sc[t*SC_STRIDE + j] - m);
            sc[t*SC_STRIDE + j] = e; s += e;
        }
        float inv = 1.f / s;
        for (int j = 0; j < TOPK; j++) sc[t*SC_STRIDE + j] *= inv;
    }
    __syncthreads();
    int d0 = (t & 3) * 32;
    float oacc[32];
    #pragma unroll
    for (int i = 0; i < 32; i++) oacc[i] = 0.f;
    for (int kc = 0; kc < TOPK/KC; kc++) {
        __syncthreads();
        for (int l = t; l < KC*HD; l += 256) {
            int kj = l / HD, d = l % HD;
            kt[kj*QS_STRIDE + d] = v[((size_t)(rb + kc*KC + kj))*DD + h*HD + d];
        }
        __syncthreads();
        for (int j = 0; j < KC; j++) {
            float p = sc[qi*SC_STRIDE + kc*KC + j];
            #pragma unroll
            for (int dd = 0; dd < 32; dd++)
                oacc[dd] += p * kt[j*QS_STRIDE + d0 + dd];
        }
    }
    float* orow = attn + ((size_t)(rb + qt*QT + qi))*DD + h*HD + d0;
    #pragma unroll
    for (int dd = 0; dd < 32; dd++) orow[dd] = oacc[dd];
}

// ---------------- 8. mean of selected V per (b,h) -> shared attn row ----------------
__global__ void meanv_kernel(const float* __restrict__ v, float* __restrict__ attn) {
    int h = blockIdx.x, b = blockIdx.y;
    int d = threadIdx.x;
    float s = 0.f;
    for (int j = 0; j < TOPK; j++)
        s += v[((size_t)(b*TOPK + j))*DD + h*HD + d];
    attn[((size_t)(RSEL + b))*DD + h*HD + d] = s * (1.f / TOPK);
}

// ---------------- 9. add masked_input x for selected rows ----------------
__global__ void addx_kernel(const float* __restrict__ x, const int* __restrict__ gidx,
                            float* __restrict__ h) {
    int r = blockIdx.x;
    int b = r / TOPK;
    int pos = gidx[r];
    const float* xr = x + ((size_t)b*SS + pos) * DD;
    float* hr = h + (size_t)r * DD;
    for (int c = threadIdx.x; c < DD; c += 256) hr[c] += xr[c];
}

// ---------------- 10. silu(u1)*u3 in place ----------------
__global__ void silu_mul(float* __restrict__ u1, const float* __restrict__ u3, size_t n) {
    size_t i = (size_t)blockIdx.x*256 + threadIdx.x;
    if (i < n) {
        float a = u1[i];
        float s = a / (1.f + expf(-a));
        u1[i] = s * u3[i];
    }
}

// ---------------- 11. scatter rows to full (B,S,D) output ----------------
__global__ void scatter_out(const float* __restrict__ rows, const int* __restrict__ rank,
                            float* __restrict__ dout) {
    int tok = blockIdx.x;
    int b = tok / SS;
    int rk = rank[tok];
    int srow = (rk >= 0) ? (b*TOPK + rk) : (RSEL + b);
    const float4* s4 = (const float4*)(rows + (size_t)srow * DD);
    float4* d4 = (float4*)(dout + (size_t)tok * DD);
    for (int c = threadIdx.x; c < DD/4; c += 256) d4[c] = s4[c];
}

// ---------------- launch ----------------
extern "C" void kernel_launch(void* const* d_in, const int* in_sizes, int n_in,
                              void* d_out, int out_size) {
    const float* x        = (const float*)d_in[0];
    const int*   start_p  = (const int*)  d_in[1];
    const float* freqs    = (const float*)d_in[2];
    const float* router_w = (const float*)d_in[3];
    const float* wq       = (const float*)d_in[4];
    const float* wk       = (const float*)d_in[5];
    const float* wv       = (const float*)d_in[6];
    const float* wo       = (const float*)d_in[7];
    const float* w1       = (const float*)d_in[8];
    const float* w2       = (const float*)d_in[9];
    const float* w3       = (const float*)d_in[10];
    const float* attn_nw  = (const float*)d_in[11];
    const float* ffn_nw   = (const float*)d_in[12];
    float* out = (float*)d_out;

    size_t off_tw  = (size_t)BB*SS*DD;
    size_t off_idx = off_tw + (size_t)BB*SS;
    size_t osz = (size_t)out_size;

    float *tw, *xn, *q, *k, *v, *attn, *h, *hn, *u1, *u3, *outrows;
    int *idx, *rank;
    cudaGetSymbolAddress((void**)&tw,   g_tw);
    cudaGetSymbolAddress((void**)&idx,  g_idx);
    cudaGetSymbolAddress((void**)&rank, g_rank);
    cudaGetSymbolAddress((void**)&xn,   g_xn);
    cudaGetSymbolAddress((void**)&q,    g_q);
    cudaGetSymbolAddress((void**)&k,    g_k);
    cudaGetSymbolAddress((void**)&v,    g_v);
    cudaGetSymbolAddress((void**)&attn, g_attn);
    cudaGetSymbolAddress((void**)&h,    g_h);
    cudaGetSymbolAddress((void**)&hn,   g_hn);
    cudaGetSymbolAddress((void**)&u1,   g_u1);
    cudaGetSymbolAddress((void**)&u3,   g_u3);
    cudaGetSymbolAddress((void**)&outrows, g_outrows);

    int attn_smem = (QT*QS_STRIDE + KC*QS_STRIDE + QT*SC_STRIDE) * 4;
    cudaFuncSetAttribute(attn_kernel, cudaFuncAttributeMaxDynamicSharedMemorySize, attn_smem);
    cudaFuncSetAttribute(mma_gemm, cudaFuncAttributeMaxDynamicSharedMemorySize, GEMM_SMEM);

    const int MTILES_SEL = RSEL / BM;              // 4
    const int MTILES_TOT = (RTOT + BM - 1) / BM;   // 5

    // 1. router (exact fp32 -> top-k selection identical to reference)
    router_kernel<<<BB*SS, 256>>>(x, router_w, tw, out, off_tw, osz);
    // 2. top-k
    topk_kernel<<<BB, 1024>>>(tw, idx, out, off_idx, osz);
    // 3. rank map
    rank_init<<<(BB*SS + 255)/256, 256>>>(rank);
    rank_set<<<(RSEL + 255)/256, 256>>>(idx, rank);
    // 4. gather + rmsnorm(attn)
    rmsnorm_gather<<<RSEL, 256>>>(x, idx, attn_nw, xn);
    // 5. QKV projections (3xTF32 mma.sync, z batches the 3 weights)
    mma_gemm<<<dim3(DD/BN, MTILES_SEL, 3), 256, GEMM_SMEM>>>(
        xn, wq, wk, wv, q, k, v, RSEL, DD, DD);
    // 6. rotary
    rotary_kernel<<<RSEL, 256>>>(q, k, idx, freqs, start_p);
    // 7. attention over selected tokens
    attn_kernel<<<dim3(TOPK/QT, HH, BB), 256, attn_smem>>>(q, k, v, attn);
    // 8. shared row = mean of selected V
    meanv_kernel<<<dim3(HH, BB), HD>>>(v, attn);
    // 9. wo projection on 514 rows, then add masked_input
    mma_gemm<<<dim3(DD/BN, MTILES_TOT, 1), 256, GEMM_SMEM>>>(
        attn, wo, wo, wo, h, h, h, RTOT, DD, DD);
    addx_kernel<<<RSEL, 256>>>(x, idx, h);
    // 10. ffn rmsnorm
    rmsnorm_rows<<<RTOT, 256>>>(h, ffn_nw, hn);
    // 11. FFN: w1 and w3 batched in z
    mma_gemm<<<dim3(HIDDEN/BN, MTILES_TOT, 2), 256, GEMM_SMEM>>>(
        hn, w1, w3, w3, u1, u3, u3, RTOT, DD, HIDDEN);
    {
        size_t n = (size_t)RTOT * HIDDEN;
        silu_mul<<<(unsigned)((n + 255)/256), 256>>>(u1, u3, n);
    }
    mma_gemm<<<dim3(DD/BN, MTILES_TOT, 1), 256, GEMM_SMEM>>>(
        u1, w2, w2, w2, outrows, outrows, outrows, RTOT, HIDDEN, DD);
    // 12. scatter to (B,S,D)
    scatter_out<<<BB*SS, 256>>>(outrows, rank, out);
}